// round 3
// baseline (speedup 1.0000x reference)
#include <cuda_runtime.h>

#define NN 5000   // nodes per level
#define BB 1024   // batch
#define KK 16     // fan-in
#define NLEV 9    // level applications
#define NEG_SLOPE 0.1f

// 3-byte split activation storage, [N, B] node-major, ping-pong.
// hi = top 16 bits of fp32 (bf16-equivalent), lo = next mantissa byte.
// Reconstruction: bits = (hi<<16) | (lo<<8) | lo  (duplicated low byte: <1.5e-5 rel noise)
__device__ __align__(16) unsigned short g_hi[2][NN * BB];   // 2 x 10.24 MB
__device__ __align__(16) unsigned char  g_lo[2][NN * BB];   // 2 x  5.12 MB

__device__ __forceinline__ unsigned int round_bits(float v) {
    // round fp32 at the discarded-byte boundary (carry propagates naturally)
    return __float_as_uint(v) + 0x80u;
}

// ---------------------------------------------------------------------------
// Transpose + split input x [B, N] -> planes[0] [N, B]
// ---------------------------------------------------------------------------
__global__ void tin_kernel(const float* __restrict__ x) {
    __shared__ float tile[32][33];
    int n = blockIdx.x * 32 + threadIdx.x;
    int b = blockIdx.y * 32 + threadIdx.y;       // B divisible by 32
    if (n < NN) tile[threadIdx.y][threadIdx.x] = x[b * NN + n];
    __syncthreads();
    int b2 = blockIdx.y * 32 + threadIdx.x;
    int n2 = blockIdx.x * 32 + threadIdx.y;
    if (n2 < NN) {
        unsigned int bits = round_bits(tile[threadIdx.x][threadIdx.y]);
        g_hi[0][n2 * BB + b2] = (unsigned short)(bits >> 16);
        g_lo[0][n2 * BB + b2] = (unsigned char)(bits >> 8);
    }
}

// ---------------------------------------------------------------------------
// One level. One block per node; 256 threads x 4 batch elems.
// Gather: per k, 8 B from hi plane (uint2) + 4 B from lo plane (u32) = 12 B
// per 4 activations (vs 16 B fp32). Fully coalesced 256B/128B warp rows.
// ---------------------------------------------------------------------------
__global__ __launch_bounds__(256) void level_kernel(int ssel,
                                                    const int* __restrict__ sidx,
                                                    const float* __restrict__ w,
                                                    const float* __restrict__ bias) {
    const unsigned short* __restrict__ hi = g_hi[ssel];
    const unsigned char*  __restrict__ lo = g_lo[ssel];
    unsigned short* __restrict__ dhi = g_hi[ssel ^ 1];
    unsigned char*  __restrict__ dlo = g_lo[ssel ^ 1];

    int n = blockIdx.x;
    int t = threadIdx.x;

    __shared__ int   s_idx[KK];
    __shared__ float s_w[KK];
    if (t < KK) {
        s_idx[t] = sidx[n * KK + t];
        s_w[t]   = w[n * KK + t];
    }
    __syncthreads();

    float bv = bias[n];
    float a0 = bv, a1 = bv, a2 = bv, a3 = bv;

#pragma unroll
    for (int k = 0; k < KK; k++) {
        int s = s_idx[k];
        uint2        h = __ldg(reinterpret_cast<const uint2*>(hi + s * BB) + t);
        unsigned int l = __ldg(reinterpret_cast<const unsigned int*>(lo + s * BB) + t);
        float wk = s_w[k];
        // one PRMT per value: [h_hi, h_lo, l_i, l_i]
        a0 = fmaf(__uint_as_float(__byte_perm(h.x, l, 0x1044)), wk, a0);
        a1 = fmaf(__uint_as_float(__byte_perm(h.x, l, 0x3255)), wk, a1);
        a2 = fmaf(__uint_as_float(__byte_perm(h.y, l, 0x1066)), wk, a2);
        a3 = fmaf(__uint_as_float(__byte_perm(h.y, l, 0x3277)), wk, a3);
    }

    a0 = a0 > 0.0f ? a0 : NEG_SLOPE * a0;
    a1 = a1 > 0.0f ? a1 : NEG_SLOPE * a1;
    a2 = a2 > 0.0f ? a2 : NEG_SLOPE * a2;
    a3 = a3 > 0.0f ? a3 : NEG_SLOPE * a3;

    unsigned int b0 = round_bits(a0);
    unsigned int b1 = round_bits(a1);
    unsigned int b2 = round_bits(a2);
    unsigned int b3 = round_bits(a3);

    // pack hi: bytes [b1.3, b1.2, b0.3, b0.2], etc.
    unsigned int h01 = __byte_perm(b0, b1, 0x7632);
    unsigned int h23 = __byte_perm(b2, b3, 0x7632);
    // pack lo: byte1 of each value
    unsigned int t01 = __byte_perm(b0, b1, 0x0051);
    unsigned int t23 = __byte_perm(b2, b3, 0x0051);
    unsigned int lpk = __byte_perm(t01, t23, 0x5410);

    reinterpret_cast<uint2*>(dhi + n * BB)[t] = make_uint2(h01, h23);
    reinterpret_cast<unsigned int*>(dlo + n * BB)[t] = lpk;
}

// ---------------------------------------------------------------------------
// Reconstruct + transpose final planes -> out [B, N]
// ---------------------------------------------------------------------------
__global__ void tout_kernel(int sel, float* __restrict__ out) {
    __shared__ float tile[32][33];
    int b = blockIdx.x * 32 + threadIdx.x;
    int n = blockIdx.y * 32 + threadIdx.y;
    if (n < NN) {
        unsigned int h = g_hi[sel][n * BB + b];
        unsigned int l = g_lo[sel][n * BB + b];
        tile[threadIdx.y][threadIdx.x] = __uint_as_float((h << 16) | (l << 8) | l);
    }
    __syncthreads();
    int n2 = blockIdx.y * 32 + threadIdx.x;
    int b2 = blockIdx.x * 32 + threadIdx.y;
    if (n2 < NN) out[b2 * NN + n2] = tile[threadIdx.x][threadIdx.y];
}

// ---------------------------------------------------------------------------
extern "C" void kernel_launch(void* const* d_in, const int* in_sizes, int n_in,
                              void* d_out, int out_size) {
    const float* x    = (const float*)d_in[0];   // [B, N] fp32
    const int*   sidx = (const int*)d_in[1];     // [NLEV, N, K] int32
    const float* w    = (const float*)d_in[2];   // [NLEV, N, K] fp32
    const float* bias = (const float*)d_in[3];   // [NLEV, N]    fp32
    float* out = (float*)d_out;                  // [B, N] fp32

    dim3 tblk(32, 32);
    dim3 tin_grid((NN + 31) / 32, BB / 32);
    tin_kernel<<<tin_grid, tblk>>>(x);

    for (int l = 0; l < NLEV; l++) {
        level_kernel<<<NN, 256>>>(l & 1,
                                  sidx + (size_t)l * NN * KK,
                                  w    + (size_t)l * NN * KK,
                                  bias + (size_t)l * NN);
    }

    dim3 tout_grid(BB / 32, (NN + 31) / 32);
    tout_kernel<<<tout_grid, tblk>>>(NLEV & 1, out);
}

// round 5
// speedup vs baseline: 1.4740x; 1.4740x over previous
#include <cuda_runtime.h>
#include <cuda_fp16.h>

#define NN 5000   // nodes per level
#define BB 1024   // batch
#define KK 16     // fan-in
#define NLEV 9    // level applications
#define NEG_SLOPE 0.1f

// fp16 activation planes, [N, B] node-major, ping-pong: 2 x 10.24 MB.
__device__ __align__(16) __half g_act[2][NN * BB];

// ---------------------------------------------------------------------------
// Transpose input x [B, N] fp32 -> g_act[0] [N, B] fp16 (RTN)
// ---------------------------------------------------------------------------
__global__ void tin_kernel(const float* __restrict__ x) {
    __shared__ float tile[32][33];
    int n = blockIdx.x * 32 + threadIdx.x;
    int b = blockIdx.y * 32 + threadIdx.y;        // B divisible by 32
    if (n < NN) tile[threadIdx.y][threadIdx.x] = x[b * NN + n];
    __syncthreads();
    int b2 = blockIdx.y * 32 + threadIdx.x;
    int n2 = blockIdx.x * 32 + threadIdx.y;
    if (n2 < NN) g_act[0][n2 * BB + b2] = __float2half_rn(tile[threadIdx.x][threadIdx.y]);
}

// ---------------------------------------------------------------------------
// One level. One block per node; 128 threads x 8 batch elems.
// Per k: ONE LDG.128 (8 fp16) per thread. fp32 accumulation.
// ---------------------------------------------------------------------------
__global__ __launch_bounds__(128) void level_kernel(int ssel,
                                                    const int* __restrict__ sidx,
                                                    const float* __restrict__ w,
                                                    const float* __restrict__ bias) {
    const __half* __restrict__ src = g_act[ssel];
    __half*       __restrict__ dst = g_act[ssel ^ 1];

    int n = blockIdx.x;
    int t = threadIdx.x;

    __shared__ int   s_idx[KK];
    __shared__ float s_w[KK];
    if (t < KK) {
        s_idx[t] = sidx[n * KK + t];
        s_w[t]   = w[n * KK + t];
    }
    __syncthreads();

    float bv = bias[n];
    float a0 = bv, a1 = bv, a2 = bv, a3 = bv;
    float a4 = bv, a5 = bv, a6 = bv, a7 = bv;

#pragma unroll
    for (int k = 0; k < KK; k++) {
        const float4* row = reinterpret_cast<const float4*>(src + s_idx[k] * BB);
        float4 v = __ldg(row + t);                 // 8 halves
        float wk = s_w[k];
        float2 f0 = __half22float2(*reinterpret_cast<const __half2*>(&v.x));
        float2 f1 = __half22float2(*reinterpret_cast<const __half2*>(&v.y));
        float2 f2 = __half22float2(*reinterpret_cast<const __half2*>(&v.z));
        float2 f3 = __half22float2(*reinterpret_cast<const __half2*>(&v.w));
        a0 = fmaf(f0.x, wk, a0);  a1 = fmaf(f0.y, wk, a1);
        a2 = fmaf(f1.x, wk, a2);  a3 = fmaf(f1.y, wk, a3);
        a4 = fmaf(f2.x, wk, a4);  a5 = fmaf(f2.y, wk, a5);
        a6 = fmaf(f3.x, wk, a6);  a7 = fmaf(f3.y, wk, a7);
    }

    a0 = a0 > 0.0f ? a0 : NEG_SLOPE * a0;
    a1 = a1 > 0.0f ? a1 : NEG_SLOPE * a1;
    a2 = a2 > 0.0f ? a2 : NEG_SLOPE * a2;
    a3 = a3 > 0.0f ? a3 : NEG_SLOPE * a3;
    a4 = a4 > 0.0f ? a4 : NEG_SLOPE * a4;
    a5 = a5 > 0.0f ? a5 : NEG_SLOPE * a5;
    a6 = a6 > 0.0f ? a6 : NEG_SLOPE * a6;
    a7 = a7 > 0.0f ? a7 : NEG_SLOPE * a7;

    __half2 h0 = __floats2half2_rn(a0, a1);
    __half2 h1 = __floats2half2_rn(a2, a3);
    __half2 h2 = __floats2half2_rn(a4, a5);
    __half2 h3 = __floats2half2_rn(a6, a7);

    float4 o;
    o.x = __uint_as_float(*reinterpret_cast<unsigned int*>(&h0));
    o.y = __uint_as_float(*reinterpret_cast<unsigned int*>(&h1));
    o.z = __uint_as_float(*reinterpret_cast<unsigned int*>(&h2));
    o.w = __uint_as_float(*reinterpret_cast<unsigned int*>(&h3));
    reinterpret_cast<float4*>(dst + n * BB)[t] = o;
}

// ---------------------------------------------------------------------------
// Reconstruct + transpose final plane -> out [B, N] fp32
// ---------------------------------------------------------------------------
__global__ void tout_kernel(int sel, float* __restrict__ out) {
    __shared__ float tile[32][33];
    int b = blockIdx.x * 32 + threadIdx.x;
    int n = blockIdx.y * 32 + threadIdx.y;
    if (n < NN) tile[threadIdx.y][threadIdx.x] = __half2float(g_act[sel][n * BB + b]);
    __syncthreads();
    int n2 = blockIdx.y * 32 + threadIdx.x;
    int b2 = blockIdx.x * 32 + threadIdx.y;
    if (n2 < NN) out[b2 * NN + n2] = tile[threadIdx.x][threadIdx.y];
}

// ---------------------------------------------------------------------------
extern "C" void kernel_launch(void* const* d_in, const int* in_sizes, int n_in,
                              void* d_out, int out_size) {
    const float* x    = (const float*)d_in[0];   // [B, N] fp32
    const int*   sidx = (const int*)d_in[1];     // [NLEV, N, K] int32
    const float* w    = (const float*)d_in[2];   // [NLEV, N, K] fp32
    const float* bias = (const float*)d_in[3];   // [NLEV, N]    fp32
    float* out = (float*)d_out;                  // [B, N] fp32

    dim3 tblk(32, 32);
    dim3 tin_grid((NN + 31) / 32, BB / 32);
    tin_kernel<<<tin_grid, tblk>>>(x);

    for (int l = 0; l < NLEV; l++) {
        level_kernel<<<NN, 128>>>(l & 1,
                                  sidx + (size_t)l * NN * KK,
                                  w    + (size_t)l * NN * KK,
                                  bias + (size_t)l * NN);
    }

    dim3 tout_grid(BB / 32, (NN + 31) / 32);
    tout_kernel<<<tout_grid, tblk>>>(NLEV & 1, out);
}